// round 17
// baseline (speedup 1.0000x reference)
#include <cuda_runtime.h>
#include <cuda_bf16.h>
#include <cstdint>

// ---------------- problem constants ----------------
#define B     512
#define C_IN  12
#define T_IN  5000
#define T1    496      // (5000-50)/10+1
#define T2    95       // (496-25)/5+1
#define NF    32
#define LAT   32
#define HID   64
#define EPSV  1e-5f
#define XTR   5168     // padded t_in rows per batch for conv1 A slabs (>= 3840+1328)

// ---------------- scratch (static device memory; no allocation) ----------------
__device__ float g_y1t[B * 512 * 32];      // conv1 raw output T-MAJOR [b][t][oc] (rows >= T1 garbage)
__device__ float g_y2t[B * T2 * NF];       // conv2 raw output TRANSPOSED [b][t][f]
__device__ float g_xt[B * T2 * LAT];       // post proj+LN [b][t][l]
__device__ float g_stats1[64];             // sum[32], sumsq[32]
__device__ float g_stats2[64];

// pre-split bf16 operands
__device__ unsigned short g_xth[B * XTR * 12], g_xtl[B * XTR * 12]; // x T-MAJOR [b][tin][c] hi/lo, tin>=5000 zero
__device__ unsigned short g_w1fh[32 * 640], g_w1fl[32 * 640];       // w1 flat [oc][kk], kk=k*12+c, kk>=600 zero
__device__ unsigned short g_zth[B * 512 * 32], g_ztl[B * 512 * 32]; // z transposed [b][tt][c] (tt>=496 zero)
__device__ unsigned short g_w2h[32 * 800], g_w2l[32 * 800];         // [oc][kk], kk=k*32+c

// mma.sync m16n8k16, bf16 in, fp32 accum (sm_80+ PTX; HMMA on Blackwell)
#define MMA16(c, a, b) asm volatile( \
    "mma.sync.aligned.m16n8k16.row.col.f32.bf16.bf16.f32 " \
    "{%0,%1,%2,%3}, {%4,%5,%6,%7}, {%8,%9}, {%0,%1,%2,%3};" \
    : "+f"((c)[0]), "+f"((c)[1]), "+f"((c)[2]), "+f"((c)[3]) \
    : "r"((a)[0]), "r"((a)[1]), "r"((a)[2]), "r"((a)[3]), "r"((b)[0]), "r"((b)[1]))

__device__ __forceinline__ void split_bf16(float v, unsigned short& h, unsigned short& l) {
    __nv_bfloat16 hb = __float2bfloat16(v);
    h = __bfloat16_as_ushort(hb);
    l = __bfloat16_as_ushort(__float2bfloat16(v - __bfloat162float(hb)));
}

__device__ __forceinline__ uint32_t smem_u32(const void* p) {
    uint32_t a;
    asm("{ .reg .u64 t; cvta.to.shared.u64 t, %1; cvt.u32.u64 %0, t; }" : "=r"(a) : "l"(p));
    return a;
}
__device__ __forceinline__ void cpa16(uint32_t d, const void* s) {
    asm volatile("cp.async.ca.shared.global [%0], [%1], 16;" :: "r"(d), "l"(s));
}
__device__ __forceinline__ void cpa8(uint32_t d, const void* s) {
    asm volatile("cp.async.ca.shared.global [%0], [%1], 8;" :: "r"(d), "l"(s));
}
#define CP_COMMIT() asm volatile("cp.async.commit_group;" ::: "memory")
#define CP_WAIT0()  asm volatile("cp.async.wait_group 0;" ::: "memory")
#define CP_WAIT1()  asm volatile("cp.async.wait_group 1;" ::: "memory")

// ---------------- prep (merged): zero stats + split/transpose x, w1, w2 ----------------
__global__ void prep_all_kernel(const float* __restrict__ x,
                                const float* __restrict__ w1,
                                const float* __restrict__ w2) {
    const int gid = blockIdx.x * blockDim.x + threadIdx.x;
    const int nth = gridDim.x * blockDim.x;

    if (gid < 64) { g_stats1[gid] = 0.f; g_stats2[gid] = 0.f; }

    // w1: [oc][c][50] -> flat [oc][kk=k*12+c] (640 padded, >=600 zero)
    for (int i = gid; i < 32 * 640; i += nth) {
        int oc = i / 640, kk = i - oc * 640;
        float v = 0.f;
        if (kk < 600) {
            int k = kk / 12, c = kk - k * 12;
            v = w1[oc * 600 + c * 50 + k];
        }
        split_bf16(v, g_w1fh[i], g_w1fl[i]);
    }
    // w2: [oc][c][25] -> [oc][k*32+c]
    for (int i = gid; i < 32 * 800; i += nth) {
        int oc = i / 800, r = i - oc * 800;
        int k = r >> 5, c = r & 31;
        split_bf16(w2[oc * 800 + c * 25 + k], g_w2h[i], g_w2l[i]);
    }
    // x: transpose to [b][tin][c] + split (tin >= 5000 zero)
    for (int i = gid; i < B * XTR; i += nth) {
        int b = i / XTR, tin = i - b * XTR;
        unsigned short h[12], l[12];
        if (tin < T_IN) {
#pragma unroll
            for (int c = 0; c < 12; c++)
                split_bf16(x[(b * C_IN + c) * T_IN + tin], h[c], l[c]);
        } else {
#pragma unroll
            for (int c = 0; c < 12; c++) { h[c] = 0; l[c] = 0; }
        }
        uint2* dh = (uint2*)(g_xth + (size_t)i * 12);
        uint2* dl = (uint2*)(g_xtl + (size_t)i * 12);
#pragma unroll
        for (int p = 0; p < 3; p++) {
            dh[p] = make_uint2(((uint32_t)h[4*p+1] << 16) | h[4*p],
                               ((uint32_t)h[4*p+3] << 16) | h[4*p+2]);
            dl[p] = make_uint2(((uint32_t)l[4*p+1] << 16) | l[4*p],
                               ((uint32_t)l[4*p+3] << 16) | l[4*p+2]);
        }
    }
}

// ---------------- conv1 as single flat GEMM (K=640, bf16 hi/lo) + BN1 stats ----------------
// grid (4, 512): x = t-tile of 128 outputs, y = batch. 128 threads (4 warps x 2 m16 tiles).
// A[m][kk] = xslab[m*120 + kk] (contiguous im2col, word stride 60 -> conflict-free).
// Weights double-buffered in 8 chunks of 80 kk (5 k16 steps each); kk>=600 zero.
// smem: [0,31872) A hi; [31872,63744) A lo; [63744,+2x11264) w bufs (rows padded 88 ush); stats.
#define C1_SMEM (63744 + 22528 + 256)
__global__ void __launch_bounds__(128) conv1_mma_kernel() {
    extern __shared__ __align__(16) char sm1[];
    unsigned short* xah = (unsigned short*)(sm1);
    unsigned short* xal = (unsigned short*)(sm1 + 31872);
    float* s_sum = (float*)(sm1 + 86272);
    float* s_sq  = s_sum + 32;

    const int tid  = threadIdx.x;
    const int w    = tid >> 5;
    const int lane = tid & 31;
    const int g    = lane >> 2;
    const int q    = lane & 3;
    const int b    = blockIdx.y;
    const int t0   = blockIdx.x * 128;

    if (tid < 32) { s_sum[tid] = 0.f; s_sq[tid] = 0.f; }

    // stage weight chunk ch into buffer buf (32 oc x 80 ushort data, padded rows of 88)
    auto stageW = [&](int ch, int buf) {
        const char* swh = (const char*)(g_w1fh) + ch * 160;   // row stride 1280 B
        const char* swl = (const char*)(g_w1fl) + ch * 160;
        uint32_t dwh = smem_u32(sm1 + 63744 + buf * 11264);
        uint32_t dwl = dwh + 5632;
        for (int i = tid; i < 320; i += 128) {
            int oc = i / 10, j = i - oc * 10;
            cpa16(dwh + oc * 176 + j * 16, swh + oc * 1280 + j * 16);
            cpa16(dwl + oc * 176 + j * 16, swl + oc * 1280 + j * 16);
        }
        CP_COMMIT();
    };

    // stage A slab once: 15936 elems = 3984 x 8B per array
    {
        const char* sxh = (const char*)(g_xth + ((size_t)b * XTR + t0 * 10) * 12);
        const char* sxl = (const char*)(g_xtl + ((size_t)b * XTR + t0 * 10) * 12);
        uint32_t dxh = smem_u32(xah);
        uint32_t dxl = smem_u32(xal);
        for (int i = tid; i < 3984; i += 128) {
            cpa8(dxh + i * 8, sxh + i * 8);
            cpa8(dxl + i * 8, sxl + i * 8);
        }
    }
    stageW(0, 0);   // group 0 = A slab + W chunk 0

    float acc[2][4][4] = {};
    const uint32_t* XH = (const uint32_t*)xah;
    const uint32_t* XL = (const uint32_t*)xal;

    for (int ch = 0; ch < 8; ch++) {
        const int buf = ch & 1;
        if (ch + 1 < 8) { stageW(ch + 1, buf ^ 1); CP_WAIT1(); }
        else            { CP_WAIT0(); }
        __syncthreads();

        const uint32_t* WBH = (const uint32_t*)(sm1 + 63744 + buf * 11264);
        const uint32_t* WBL = (const uint32_t*)(sm1 + 63744 + buf * 11264 + 5632);

#pragma unroll
        for (int ksl = 0; ksl < 5; ksl++) {
            const int s = ch * 5 + ksl;
            uint32_t ah[2][4], al[2][4];
#pragma unroll
            for (int mt = 0; mt < 2; mt++) {
                int i0 = (w * 32 + mt * 16 + g) * 60 + s * 8 + q;
                ah[mt][0] = XH[i0];       ah[mt][1] = XH[i0 + 480];
                ah[mt][2] = XH[i0 + 4];   ah[mt][3] = XH[i0 + 484];
                al[mt][0] = XL[i0];       al[mt][1] = XL[i0 + 480];
                al[mt][2] = XL[i0 + 4];   al[mt][3] = XL[i0 + 484];
            }
#pragma unroll
            for (int nt = 0; nt < 4; nt++) {
                int bi = (nt * 8 + g) * 44 + 8 * ksl + q;
                uint32_t bhf[2] = { WBH[bi], WBH[bi + 4] };
                uint32_t blf[2] = { WBL[bi], WBL[bi + 4] };
#pragma unroll
                for (int mt = 0; mt < 2; mt++) {
                    MMA16(acc[mt][nt], ah[mt], bhf);
                    MMA16(acc[mt][nt], ah[mt], blf);
                    MMA16(acc[mt][nt], al[mt], bhf);
                }
            }
        }
        __syncthreads();   // all warps done with buf before restaging
    }

    // epilogue: T-MAJOR store g_y1t[(b*512 + t)*32 + oc] + stats
    float psum[4][2] = {}, psq[4][2] = {};
#pragma unroll
    for (int mt = 0; mt < 2; mt++) {
#pragma unroll
        for (int rr = 0; rr < 2; rr++) {
            int t = t0 + w * 32 + mt * 16 + g + rr * 8;
            if (t < T1) {
                float* drow = g_y1t + (b * 512 + t) * 32;
#pragma unroll
                for (int nt = 0; nt < 4; nt++) {
#pragma unroll
                    for (int j = 0; j < 2; j++) {
                        float v = acc[mt][nt][rr * 2 + j];
                        drow[nt * 8 + q * 2 + j] = v;
                        psum[nt][j] += v;
                        psq[nt][j]  += v * v;
                    }
                }
            }
        }
    }
#pragma unroll
    for (int nt = 0; nt < 4; nt++)
#pragma unroll
        for (int j = 0; j < 2; j++) {
            atomicAdd(&s_sum[nt * 8 + q * 2 + j], psum[nt][j]);
            atomicAdd(&s_sq [nt * 8 + q * 2 + j], psq[nt][j]);
        }
    __syncthreads();
    if (tid < 32) {
        atomicAdd(&g_stats1[tid],      s_sum[tid]);
        atomicAdd(&g_stats1[32 + tid], s_sq[tid]);
    }
}

// ---------------- zt prep (streaming): z = relu(bn1(y1t)) -> bf16 hi/lo, same layout ----------------
__global__ void __launch_bounds__(256) ztprep_kernel(const float* __restrict__ bn1g,
                                                     const float* __restrict__ bn1b) {
    __shared__ float scs[32], shs[32];
    const int tid = threadIdx.x;
    if (tid < 32) {
        const float nInv = 1.f / (float)(B * T1);
        const float mean = g_stats1[tid] * nInv;
        const float var  = g_stats1[32 + tid] * nInv - mean * mean;
        const float sc   = bn1g[tid] * rsqrtf(var + EPSV);
        scs[tid] = sc;
        shs[tid] = bn1b[tid] - mean * sc;
    }
    __syncthreads();

    const int idx8 = blockIdx.x * 256 + tid;
    const int base = idx8 * 8;
    const int c0   = base & 31;
    const int tt   = (base >> 5) & 511;

    unsigned short h[8], l[8];
    if (tt < T1) {
        float4 f0 = *(const float4*)(g_y1t + base);
        float4 f1 = *(const float4*)(g_y1t + base + 4);
        float vv[8] = { f0.x, f0.y, f0.z, f0.w, f1.x, f1.y, f1.z, f1.w };
#pragma unroll
        for (int i = 0; i < 8; i++) {
            float v = fmaf(vv[i], scs[c0 + i], shs[c0 + i]);
            v = v > 0.f ? v : 0.f;
            split_bf16(v, h[i], l[i]);
        }
    } else {
#pragma unroll
        for (int i = 0; i < 8; i++) { h[i] = 0; l[i] = 0; }
    }
    uint4 ph = make_uint4(((uint32_t)h[1] << 16) | h[0], ((uint32_t)h[3] << 16) | h[2],
                          ((uint32_t)h[5] << 16) | h[4], ((uint32_t)h[7] << 16) | h[6]);
    uint4 pl = make_uint4(((uint32_t)l[1] << 16) | l[0], ((uint32_t)l[3] << 16) | l[2],
                          ((uint32_t)l[5] << 16) | l[4], ((uint32_t)l[7] << 16) | l[6]);
    *(uint4*)(g_zth + base) = ph;
    *(uint4*)(g_ztl + base) = pl;
}

// ---------------- conv2 via single K=800 GEMM, one block per batch ----------------
#define C2_SMEM 104704
__global__ void __launch_bounds__(192) conv2_mma_kernel() {
    extern __shared__ __align__(16) char sm[];
    unsigned short* zah = (unsigned short*)(sm);
    unsigned short* zal = (unsigned short*)(sm + 40960);
    float* s_sum = (float*)(sm + 104448);
    float* s_sq  = s_sum + 32;

    const int tid  = threadIdx.x;
    const int w    = tid >> 5;
    const int lane = tid & 31;
    const int g    = lane >> 2;
    const int q    = lane & 3;
    const int b    = blockIdx.x;

    if (tid < 32) { s_sum[tid] = 0.f; s_sq[tid] = 0.f; }

    auto stageW = [&](int ch, int buf) {
        const char* swh = (const char*)(g_w2h) + ch * 160;
        const char* swl = (const char*)(g_w2l) + ch * 160;
        uint32_t dwh = smem_u32(sm + 81920 + buf * 11264);
        uint32_t dwl = dwh + 5632;
        for (int i = tid; i < 320; i += 192) {
            int oc = i / 10, j = i - oc * 10;
            cpa16(dwh + oc * 176 + j * 16, swh + oc * 1600 + j * 16);
            cpa16(dwl + oc * 176 + j * 16, swl + oc * 1600 + j * 16);
        }
        CP_COMMIT();
    };

    {
        const char* szh = (const char*)(g_zth + b * 512 * 32);
        const char* szl = (const char*)(g_ztl + b * 512 * 32);
        uint32_t dzh = smem_u32(zah);
        uint32_t dzl = smem_u32(zal);
        for (int i = tid; i < 2048; i += 192) {
            int r = i >> 2, j = i & 3;
            cpa16(dzh + r * 80 + j * 16, szh + r * 64 + j * 16);
            cpa16(dzl + r * 80 + j * 16, szl + r * 64 + j * 16);
        }
    }
    stageW(0, 0);

    float acc[4][4] = {};
    const uint32_t* ZAH = (const uint32_t*)zah;
    const uint32_t* ZAL = (const uint32_t*)zal;

    const int mrow  = w * 16 + g;
    const int base0 = mrow * 100 + q;
    const int base1 = (mrow + 8) * 100 + q;

    for (int ch = 0; ch < 10; ch++) {
        const int buf = ch & 1;
        if (ch + 1 < 10) { stageW(ch + 1, buf ^ 1); CP_WAIT1(); }
        else             { CP_WAIT0(); }
        __syncthreads();

        const uint32_t* WBH = (const uint32_t*)(sm + 81920 + buf * 11264);
        const uint32_t* WBL = (const uint32_t*)(sm + 81920 + buf * 11264 + 5632);

#pragma unroll
        for (int ksl = 0; ksl < 5; ksl++) {
            const int s  = ch * 5 + ksl;
            const int ao = (s >> 1) * 20 + (s & 1) * 8;
            uint32_t ah[4], al[4];
            ah[0] = ZAH[base0 + ao];     ah[1] = ZAH[base1 + ao];
            ah[2] = ZAH[base0 + ao + 4]; ah[3] = ZAH[base1 + ao + 4];
            al[0] = ZAL[base0 + ao];     al[1] = ZAL[base1 + ao];
            al[2] = ZAL[base0 + ao + 4]; al[3] = ZAL[base1 + ao + 4];
#pragma unroll
            for (int nt = 0; nt < 4; nt++) {
                int bi = (nt * 8 + g) * 44 + 8 * ksl + q;
                uint32_t bhf[2] = { WBH[bi], WBH[bi + 4] };
                uint32_t blf[2] = { WBL[bi], WBL[bi + 4] };
                MMA16(acc[nt], ah, bhf);
                MMA16(acc[nt], ah, blf);
                MMA16(acc[nt], al, bhf);
            }
        }
        __syncthreads();
    }

    float psum[4][2] = {}, psq[4][2] = {};
#pragma unroll
    for (int rr = 0; rr < 2; rr++) {
        int t = mrow + rr * 8;
        if (t < T2) {
#pragma unroll
            for (int nt = 0; nt < 4; nt++) {
#pragma unroll
                for (int j = 0; j < 2; j++) {
                    float v = acc[nt][rr * 2 + j];
                    int oc = nt * 8 + q * 2 + j;
                    g_y2t[(b * T2 + t) * NF + oc] = v;
                    psum[nt][j] += v;
                    psq[nt][j]  += v * v;
                }
            }
        }
    }
#pragma unroll
    for (int nt = 0; nt < 4; nt++)
#pragma unroll
        for (int j = 0; j < 2; j++) {
            atomicAdd(&s_sum[nt * 8 + q * 2 + j], psum[nt][j]);
            atomicAdd(&s_sq [nt * 8 + q * 2 + j], psq[nt][j]);
        }
    __syncthreads();
    if (tid < 32) {
        atomicAdd(&g_stats2[tid],      s_sum[tid]);
        atomicAdd(&g_stats2[32 + tid], s_sq[tid]);
    }
}

// ---------------- projection + layernorm (BN2 finalize folded in) ----------------
__global__ void projln_kernel(const float* __restrict__ pw,
                              const float* __restrict__ pb,
                              const float* __restrict__ lng,
                              const float* __restrict__ lnb,
                              const float* __restrict__ bn2g,
                              const float* __restrict__ bn2b) {
    __shared__ float pws[32 * 33];
    const int tid = threadIdx.x;
    for (int idx = tid; idx < 1024; idx += blockDim.x)
        pws[(idx & 31) * 33 + (idx >> 5)] = pw[idx];
    __syncthreads();

    const int lane   = tid & 31;
    const int warpId = (blockIdx.x * blockDim.x + tid) >> 5;
    const int nw     = (gridDim.x * blockDim.x) >> 5;

    const float nInv = 1.f / (float)(B * T2);
    const float mean = g_stats2[lane] * nInv;
    const float var  = g_stats2[32 + lane] * nInv - mean * mean;
    const float s2   = bn2g[lane] * rsqrtf(var + EPSV);
    const float sh2  = bn2b[lane] - mean * s2;

    const float pbv = pb[lane];
    const float lg  = lng[lane], lb = lnb[lane];

    for (int task = warpId; task < B * T2; task += nw) {
        float v = g_y2t[task * NF + lane];
        v = fmaf(v, s2, sh2);
        v = v > 0.f ? v : 0.f;

        float a = pbv;
#pragma unroll
        for (int f = 0; f < 32; f++)
            a = fmaf(__shfl_sync(0xffffffffu, v, f), pws[f * 33 + lane], a);

        float s = a;
#pragma unroll
        for (int off = 16; off > 0; off >>= 1) s += __shfl_xor_sync(0xffffffffu, s, off);
        float mean2 = s * (1.f / 32.f);
        float d = a - mean2;
        float qq = d * d;
#pragma unroll
        for (int off = 16; off > 0; off >>= 1) qq += __shfl_xor_sync(0xffffffffu, qq, off);
        float var2 = qq * (1.f / 32.f);
        g_xt[task * LAT + lane] = fmaf(d * rsqrtf(var2 + EPSV), lg, lb);
    }
}

// ---------------- PLRNN scan + pool + output projection ----------------
__global__ void recur_kernel(const float* __restrict__ Ain,
                             const float* __restrict__ Win,
                             const float* __restrict__ hbin,
                             const float* __restrict__ owin,
                             const float* __restrict__ obin,
                             float* __restrict__ out) {
    __shared__ float As[32 * 33];
    __shared__ float Ws[32 * 65];
    __shared__ float ows[32 * 33];
    __shared__ float hbs[64];

    const int tid = threadIdx.x;
    for (int idx = tid; idx < 1024; idx += 128) {
        As[(idx >> 5) * 33 + (idx & 31)]  = Ain[idx];
        ows[(idx >> 5) * 33 + (idx & 31)] = owin[idx];
    }
    for (int idx = tid; idx < 2048; idx += 128)
        Ws[(idx >> 6) * 65 + (idx & 63)] = Win[idx];
    if (tid < 64) hbs[tid] = hbin[tid];
    __syncthreads();

    const int lane = tid & 31;
    const int b    = blockIdx.x * 4 + (tid >> 5);

    float h = 0.f, sum = 0.f;
    const float* xrow = g_xt + b * T2 * LAT + lane;

    for (int t = 0; t < T2; t++) {
        float xv = xrow[t * LAT];
        float lin = 0.f;
        float p0 = hbs[lane];
        float p1 = hbs[32 + lane];
#pragma unroll
        for (int m = 0; m < 32; m++) {
            float hm = __shfl_sync(0xffffffffu, h, m);
            lin = fmaf(As[lane * 33 + m],      hm, lin);
            p0  = fmaf(Ws[m * 65 + lane],      hm, p0);
            p1  = fmaf(Ws[m * 65 + 32 + lane], hm, p1);
        }
        float r0 = fmaxf(p0, 0.f);
        float r1 = fmaxf(p1, 0.f);
        float nl = 0.f;
#pragma unroll
        for (int j = 0; j < 32; j++)
            nl = fmaf(__shfl_sync(0xffffffffu, r0, j), Ws[lane * 65 + j], nl);
#pragma unroll
        for (int j = 0; j < 32; j++)
            nl = fmaf(__shfl_sync(0xffffffffu, r1, j), Ws[lane * 65 + 32 + j], nl);

        h = lin + nl + xv;
        sum += h;
    }

    float pooled = sum * (1.f / (float)T2);
    float o = obin[lane];
#pragma unroll
    for (int m = 0; m < 32; m++)
        o = fmaf(ows[lane * 33 + m], __shfl_sync(0xffffffffu, pooled, m), o);
    out[b * 32 + lane] = o;
}

// ---------------- launcher ----------------
extern "C" void kernel_launch(void* const* d_in, const int* in_sizes, int n_in,
                              void* d_out, int out_size) {
    const float* x       = (const float*)d_in[0];
    const float* conv1_w = (const float*)d_in[1];
    const float* bn1_g   = (const float*)d_in[3];
    const float* bn1_b   = (const float*)d_in[4];
    const float* conv2_w = (const float*)d_in[5];
    const float* bn2_g   = (const float*)d_in[7];
    const float* bn2_b   = (const float*)d_in[8];
    const float* proj_w  = (const float*)d_in[9];
    const float* proj_b  = (const float*)d_in[10];
    const float* ln_g    = (const float*)d_in[11];
    const float* ln_b    = (const float*)d_in[12];
    const float* A       = (const float*)d_in[13];
    const float* W       = (const float*)d_in[14];
    const float* h_bias  = (const float*)d_in[15];
    const float* out_w   = (const float*)d_in[16];
    const float* out_b   = (const float*)d_in[17];
    float* out = (float*)d_out;

    cudaFuncSetAttribute(conv1_mma_kernel,
                         cudaFuncAttributeMaxDynamicSharedMemorySize, C1_SMEM);
    cudaFuncSetAttribute(conv2_mma_kernel,
                         cudaFuncAttributeMaxDynamicSharedMemorySize, C2_SMEM);

    prep_all_kernel<<<4096, 256>>>(x, conv1_w, conv2_w);
    conv1_mma_kernel<<<dim3(4, B), 128, C1_SMEM>>>();
    ztprep_kernel<<<4096, 256>>>(bn1_g, bn1_b);
    conv2_mma_kernel<<<512, 192, C2_SMEM>>>();
    projln_kernel<<<512, 256>>>(proj_w, proj_b, ln_g, ln_b, bn2_g, bn2_b);
    recur_kernel<<<128, 128>>>(A, W, h_bias, out_w, out_b, out);
}